// round 16
// baseline (speedup 1.0000x reference)
#include <cuda_runtime.h>
#include <cuda_bf16.h>
#include <cuda_fp16.h>
#include <cstdint>
#include <math.h>

#define BQ   8
#define TT   1024
#define DM   1024
#define NH   16
#define DKK  64
#define FFI  4096
#define BT   (BQ*TT)   // 8192 rows
#define BHN  (BQ*NH)   // 128 (b,h) pairs
#define QKVN 3072

// ---------------- scratch (static device globals) --------------------------------
__device__ __nv_bfloat16 g_xh[BT*DM];                 // x in bf16
__device__ __nv_bfloat16 g_Wqkvh[QKVN*DM];            // [n][k] bf16 (Q cols prescaled)
__device__ __nv_bfloat16 g_Worh[DM*DM];               // Wo^T bf16
__device__ __nv_bfloat16 g_QKVh[(size_t)BT*QKVN];     // QKV bf16
__device__ __nv_bfloat16 g_Sh[(size_t)BHN*TT*TT];     // P bf16 (256 MB)
__device__ __nv_bfloat16 g_parth[BT*DM];              // attention out bf16
__device__ __half g_W1h[FFI*DM];                      // W1 fp16 [f][d]
__device__ __half g_W2h[DM*FFI];                      // W2 fp16 [d][f]
__device__ __half g_out1h[BT*DM];                     // out1 fp16 (GEMM A)
__device__ __half g_ffhh[(size_t)BT*FFI];             // FF hidden fp16
__device__ float g_zpart[BHN*8*TT];
__device__ float g_out1[BT*DM];                       // out1 fp32 (residual)
__device__ float g_out2[BT*DM];

// ================= helpers =======================================================
__device__ __forceinline__ uint32_t smem_to_u32(const void* p) {
    uint32_t a;
    asm("{ .reg .u64 t; cvta.to.shared.u64 t, %1; cvt.u32.u64 %0, t; }" : "=r"(a) : "l"(p));
    return a;
}
__device__ __forceinline__ float ex2f(float x) {
    float r;
    asm("ex2.approx.f32 %0, %1;" : "=f"(r) : "f"(x));
    return r;
}
__device__ __forceinline__ uint32_t pack_bf162(float lo, float hi) {
    uint32_t r;
    asm("cvt.rn.bf16x2.f32 %0, %1, %2;" : "=r"(r) : "f"(hi), "f"(lo));
    return r;
}
__device__ __forceinline__ uint32_t pack_f162(float lo, float hi) {
    uint32_t r;
    asm("cvt.rn.f16x2.f32 %0, %1, %2;" : "=r"(r) : "f"(hi), "f"(lo));
    return r;
}
__device__ __forceinline__ uint32_t bmul2(uint32_t a, uint32_t b) {
    uint32_t r;
    asm("mul.rn.bf16x2 %0, %1, %2;" : "=r"(r) : "r"(a), "r"(b));
    return r;
}
__device__ __forceinline__ void cpasync16(uint32_t dst, const void* src) {
    asm volatile("cp.async.cg.shared.global [%0], [%1], 16;" :: "r"(dst), "l"(src));
}
#define CP_COMMIT() asm volatile("cp.async.commit_group;" ::: "memory")
#define CP_WAIT(n)  asm volatile("cp.async.wait_group %0;" :: "n"(n) : "memory")

__device__ __forceinline__ void ldsm_x4(uint32_t& r0, uint32_t& r1, uint32_t& r2,
                                        uint32_t& r3, uint32_t addr) {
    asm volatile("ldmatrix.sync.aligned.m8n8.x4.shared.b16 {%0,%1,%2,%3}, [%4];"
                 : "=r"(r0), "=r"(r1), "=r"(r2), "=r"(r3) : "r"(addr));
}
__device__ __forceinline__ void ldsm_x4t(uint32_t& r0, uint32_t& r1, uint32_t& r2,
                                         uint32_t& r3, uint32_t addr) {
    asm volatile("ldmatrix.sync.aligned.m8n8.x4.trans.shared.b16 {%0,%1,%2,%3}, [%4];"
                 : "=r"(r0), "=r"(r1), "=r"(r2), "=r"(r3) : "r"(addr));
}

__device__ __forceinline__ void mma_bf16(float* c, uint32_t a0, uint32_t a1,
                                         uint32_t a2, uint32_t a3,
                                         uint32_t b0, uint32_t b1) {
    asm volatile(
        "mma.sync.aligned.m16n8k16.row.col.f32.bf16.bf16.f32 "
        "{%0,%1,%2,%3}, {%4,%5,%6,%7}, {%8,%9}, {%0,%1,%2,%3};"
        : "+f"(c[0]), "+f"(c[1]), "+f"(c[2]), "+f"(c[3])
        : "r"(a0), "r"(a1), "r"(a2), "r"(a3), "r"(b0), "r"(b1));
}
__device__ __forceinline__ void mma_fp16(float* c, uint32_t a0, uint32_t a1,
                                         uint32_t a2, uint32_t a3,
                                         uint32_t b0, uint32_t b1) {
    asm volatile(
        "mma.sync.aligned.m16n8k16.row.col.f32.f16.f16.f32 "
        "{%0,%1,%2,%3}, {%4,%5,%6,%7}, {%8,%9}, {%0,%1,%2,%3};"
        : "+f"(c[0]), "+f"(c[1]), "+f"(c[2]), "+f"(c[3])
        : "r"(a0), "r"(a1), "r"(a2), "r"(a3), "r"(b0), "r"(b1));
}

// ================= half-precision dense GEMM (R14) ===============================
#define GM_STAGE_BYTES 36864u
#define GM_SMEM_BYTES  (3*36864)

template <int EPI, int FMT>
__global__ void __launch_bounds__(256, 2) gemm_h(
    const void* __restrict__ Av, int lda,
    const void* __restrict__ Bv, int ldb,
    void* __restrict__ Cv, int ldc,
    int K,
    const float* __restrict__ bias,
    const float* __restrict__ res, int ldres)
{
    extern __shared__ uint32_t smem[];
    const int tid = threadIdx.x;
    const int wid = tid >> 5, lane = tid & 31;
    const int wm = wid >> 2, wn = wid & 3;
    const int grp = lane >> 2, kq = lane & 3;
    const int m0 = blockIdx.y * 128, n0 = blockIdx.x * 128;

    const uint16_t* Ab = (const uint16_t*)Av + (size_t)m0 * lda;
    const uint16_t* Bb = (const uint16_t*)Bv + (size_t)n0 * ldb;
    const uint32_t sbase = smem_to_u32(smem);

    const uint32_t lane15 = lane & 15;
    const uint32_t aseg = (lane >> 4) * 16;
    const uint32_t brow = ((lane >> 4) << 3) + (lane & 7);
    const uint32_t bseg = ((lane >> 3) & 1) * 16;

    float acc[4][4][4] = {};
    const int NC = K / 64;
    const int lr = tid >> 3, lseg = tid & 7;

    auto issue = [&](int c, int buf) {
        const int k0 = c * 64;
        const uint32_t sA = sbase + buf * GM_STAGE_BYTES;
        const uint32_t sB = sA + 18432u;
#pragma unroll
        for (int j = 0; j < 4; j++) {
            int rr = lr + j * 32;
            cpasync16(sA + rr * 144u + lseg * 16u, Ab + (size_t)rr * lda + k0 + lseg * 8);
            cpasync16(sB + rr * 144u + lseg * 16u, Bb + (size_t)rr * ldb + k0 + lseg * 8);
        }
    };

    issue(0, 0); CP_COMMIT();
    issue(1, 1); CP_COMMIT();

    int cbuf = 0;
    for (int c = 0; c < NC; c++) {
        if (c + 1 < NC) CP_WAIT(1); else CP_WAIT(0);
        __syncthreads();
        const uint32_t sAa = sbase + cbuf * GM_STAGE_BYTES;
        const uint32_t sBa = sAa + 18432u;
#pragma unroll
        for (int ks = 0; ks < 4; ks++) {
            uint32_t bf[4][2];
#pragma unroll
            for (int np = 0; np < 2; np++) {
                uint32_t baddr = sBa + (wn * 32 + np * 16 + brow) * 144u + ks * 32u + bseg;
                ldsm_x4(bf[np*2][0], bf[np*2][1], bf[np*2+1][0], bf[np*2+1][1], baddr);
            }
#pragma unroll
            for (int mi = 0; mi < 4; mi++) {
                uint32_t a0, a1, a2, a3;
                uint32_t aaddr = sAa + (wm * 64 + mi * 16 + lane15) * 144u + ks * 32u + aseg;
                ldsm_x4(a0, a1, a2, a3, aaddr);
#pragma unroll
                for (int ni = 0; ni < 4; ni++) {
                    if (FMT == 0) mma_bf16(acc[mi][ni], a0, a1, a2, a3, bf[ni][0], bf[ni][1]);
                    else          mma_fp16(acc[mi][ni], a0, a1, a2, a3, bf[ni][0], bf[ni][1]);
                }
            }
        }
        if (c + 2 < NC) {
            int nb = cbuf + 2; if (nb >= 3) nb -= 3;
            issue(c + 2, nb); CP_COMMIT();
        }
        cbuf = (cbuf == 2) ? 0 : cbuf + 1;
    }

    if (EPI == 4 || EPI == 2) {
        __syncthreads();
        uint32_t* pst = smem;
#pragma unroll
        for (int mi = 0; mi < 4; mi++) {
            int rl = wm * 64 + mi * 16 + grp;
#pragma unroll
            for (int ni = 0; ni < 4; ni++) {
                int cl = wn * 32 + ni * 8 + kq * 2;
                float v00 = acc[mi][ni][0], v01 = acc[mi][ni][1];
                float v10 = acc[mi][ni][2], v11 = acc[mi][ni][3];
                if (EPI == 2) {
                    int colg = n0 + cl;
                    float b0 = bias[colg], b1 = bias[colg + 1];
                    v00 = fmaxf(v00 + b0, 0.f); v01 = fmaxf(v01 + b1, 0.f);
                    v10 = fmaxf(v10 + b0, 0.f); v11 = fmaxf(v11 + b1, 0.f);
                }
                pst[rl * 68 + (cl >> 1)]       = FMT ? pack_f162(v00, v01) : pack_bf162(v00, v01);
                pst[(rl + 8) * 68 + (cl >> 1)] = FMT ? pack_f162(v10, v11) : pack_bf162(v10, v11);
            }
        }
        __syncthreads();
        uint16_t* C = (uint16_t*)Cv;
        const int fr = tid >> 4, fc = tid & 15;
#pragma unroll
        for (int p = 0; p < 8; p++) {
            int row = fr + p * 16;
            uint4 v = *(const uint4*)((const char*)smem + row * 272 + fc * 16);
            *(uint4*)(C + (size_t)(m0 + row) * ldc + n0 + fc * 8) = v;
        }
    } else {
#pragma unroll
        for (int mi = 0; mi < 4; mi++) {
            int row = m0 + wm * 64 + mi * 16 + grp;
#pragma unroll
            for (int ni = 0; ni < 4; ni++) {
                int col = n0 + wn * 32 + ni * 8 + kq * 2;
                float v00 = acc[mi][ni][0], v01 = acc[mi][ni][1];
                float v10 = acc[mi][ni][2], v11 = acc[mi][ni][3];
                float* C = (float*)Cv;
                float2 r0 = *(const float2*)(res + (size_t)row * ldres + col);
                float2 r1 = *(const float2*)(res + (size_t)(row + 8) * ldres + col);
                if (EPI == 3) {
                    float b0 = bias[col], b1 = bias[col + 1];
                    v00 += b0; v01 += b1; v10 += b0; v11 += b1;
                }
                float2 o0 = {v00 + r0.x, v01 + r0.y};
                float2 o1 = {v10 + r1.x, v11 + r1.y};
                *(float2*)(C + (size_t)row * ldc + col) = o0;
                *(float2*)(C + (size_t)(row + 8) * ldc + col) = o1;
            }
        }
    }
}

// ===== scores: P = bf16(exp2(Q'·K^T)), SMEM-staged coalesced store (R11) =========
#define SC_SMEM_BYTES 36864

__global__ void __launch_bounds__(256, 2) scores_bf(int bh0) {
    extern __shared__ uint32_t smem[];
    const int tid = threadIdx.x;
    const int wid = tid >> 5, lane = tid & 31;
    const int wm = wid >> 2, wn = wid & 3;
    const int grp = lane >> 2, kq = lane & 3;
    const int bh = bh0 + blockIdx.z, b = bh >> 4, h = bh & 15;
    const int q0 = blockIdx.y * 128, s0 = blockIdx.x * 128;

    const __nv_bfloat16* Ab = g_QKVh + (size_t)(b * TT + q0) * QKVN + h * DKK;
    const __nv_bfloat16* Bb = g_QKVh + (size_t)(b * TT + s0) * QKVN + 1024 + h * DKK;
    const uint32_t sbase = smem_to_u32(smem);
    const uint32_t sB0 = sbase + 18432u;

    const uint32_t lane15 = lane & 15;
    const uint32_t aseg = (lane >> 4) * 16;
    const uint32_t brow = ((lane >> 4) << 3) + (lane & 7);
    const uint32_t bseg = ((lane >> 3) & 1) * 16;

#pragma unroll
    for (int j = 0; j < 4; j++) {
        int idx = tid + j * 256;
        int rr = idx >> 3, seg = idx & 7;
        cpasync16(sbase + rr * 144u + seg * 16u, Ab + (size_t)rr * QKVN + seg * 8);
        cpasync16(sB0 + rr * 144u + seg * 16u, Bb + (size_t)rr * QKVN + seg * 8);
    }
    CP_COMMIT(); CP_WAIT(0);
    __syncthreads();

    float acc[4][4][4] = {};
#pragma unroll
    for (int ks = 0; ks < 4; ks++) {
        uint32_t bf[4][2];
#pragma unroll
        for (int np = 0; np < 2; np++) {
            uint32_t baddr = sB0 + (wn * 32 + np * 16 + brow) * 144u + ks * 32u + bseg;
            ldsm_x4(bf[np*2][0], bf[np*2][1], bf[np*2+1][0], bf[np*2+1][1], baddr);
        }
#pragma unroll
        for (int mi = 0; mi < 4; mi++) {
            uint32_t a0, a1, a2, a3;
            uint32_t aaddr = sbase + (wm * 64 + mi * 16 + lane15) * 144u + ks * 32u + aseg;
            ldsm_x4(a0, a1, a2, a3, aaddr);
#pragma unroll
            for (int ni = 0; ni < 4; ni++)
                mma_bf16(acc[mi][ni], a0, a1, a2, a3, bf[ni][0], bf[ni][1]);
        }
    }
    __syncthreads();   // A/B tiles dead past here; smem reused for P staging

    uint32_t* pst = smem;
    float* zsm = (float*)(smem + 8704);
    float cs0[4] = {}, cs1[4] = {};
#pragma unroll
    for (int mi = 0; mi < 4; mi++) {
        int rl = wm * 64 + mi * 16 + grp;
#pragma unroll
        for (int ni = 0; ni < 4; ni++) {
            int cl = wn * 32 + ni * 8 + kq * 2;
            float p00 = ex2f(acc[mi][ni][0]);
            float p01 = ex2f(acc[mi][ni][1]);
            float p10 = ex2f(acc[mi][ni][2]);
            float p11 = ex2f(acc[mi][ni][3]);
            cs0[ni] += p00 + p10;
            cs1[ni] += p01 + p11;
            pst[rl * 68 + (cl >> 1)]       = pack_bf162(p00, p01);
            pst[(rl + 8) * 68 + (cl >> 1)] = pack_bf162(p10, p11);
        }
    }
#pragma unroll
    for (int ni = 0; ni < 4; ni++) {
#pragma unroll
        for (int o = 16; o >= 4; o >>= 1) {
            cs0[ni] += __shfl_down_sync(0xffffffffu, cs0[ni], o);
            cs1[ni] += __shfl_down_sync(0xffffffffu, cs1[ni], o);
        }
        if (grp == 0) {
            int c = wn * 32 + ni * 8 + kq * 2;
            zsm[wm * 128 + c] = cs0[ni];
            zsm[wm * 128 + c + 1] = cs1[ni];
        }
    }
    __syncthreads();

    __nv_bfloat16* Sb = g_Sh + (size_t)bh * TT * TT;
    const int fr = tid >> 4, fc = tid & 15;
#pragma unroll
    for (int p = 0; p < 8; p++) {
        int row = fr + p * 16;
        uint4 v = *(const uint4*)((const char*)smem + row * 272 + fc * 16);
        *(uint4*)(Sb + (size_t)(q0 + row) * TT + s0 + fc * 8) = v;
    }
    if (tid < 128)
        g_zpart[(bh * 8 + blockIdx.y) * TT + s0 + tid] = zsm[tid] + zsm[128 + tid];
}

// ===== AV GEMM (bf16): part = P x (V*zinv), V direct via ldmatrix.trans (R15) ====
#define AV_STAGE_BYTES 27648u
#define AV_SMEM_BYTES (3*27648 + 2048)

__global__ void __launch_bounds__(256, 2) av_bf(int bh0) {
    extern __shared__ uint32_t smem[];
    const int tid = threadIdx.x;
    const int wid = tid >> 5, lane = tid & 31;
    const int wm = wid >> 1, wn = wid & 1;
    const int grp = lane >> 2, kq = lane & 3;
    const int bh = bh0 + blockIdx.y, b = bh >> 4, h = bh & 15;
    const int m0 = blockIdx.x * 128;

    const __nv_bfloat16* Ab = g_Sh + (size_t)bh * TT * TT + (size_t)m0 * TT;
    const __nv_bfloat16* Vb = g_QKVh + (size_t)(b * TT) * QKVN + 2048 + h * DKK;
    const uint32_t sbase = smem_to_u32(smem);

    const uint32_t lane15 = lane & 15;
    const uint32_t aseg = (lane >> 4) * 16;
    const uint32_t tkrow = (lane & 7) + ((lane >> 3) & 1) * 8;
    const uint32_t tnoff = (lane >> 4) * 16;

    uint32_t* zw = smem + 20736;
    for (int t = tid; t < 512; t += 256) {
        float z0 = 0.f, z1 = 0.f;
#pragma unroll
        for (int q = 0; q < 8; q++) {
            z0 += g_zpart[(bh * 8 + q) * TT + 2 * t];
            z1 += g_zpart[(bh * 8 + q) * TT + 2 * t + 1];
        }
        zw[t] = pack_bf162(1.f / z0, 1.f / z1);
    }

    float acc[2][4][4] = {};
    const int lr = tid >> 3, lseg = tid & 7;

    auto issue = [&](int c, int buf) {
        const int k0 = c * 64;
        const uint32_t sA = sbase + buf * AV_STAGE_BYTES;
        const uint32_t sB = sA + 18432u;
#pragma unroll
        for (int j = 0; j < 4; j++) {
            int rr = lr + j * 32;
            cpasync16(sA + rr * 144u + lseg * 16u, Ab + (size_t)rr * TT + k0 + lseg * 8);
        }
#pragma unroll
        for (int j = 0; j < 2; j++) {
            int rr = lr + j * 32;
            cpasync16(sB + rr * 144u + lseg * 16u, Vb + (size_t)(k0 + rr) * QKVN + lseg * 8);
        }
    };

    issue(0, 0); CP_COMMIT();
    issue(1, 1); CP_COMMIT();

    int cbuf = 0;
    for (int c = 0; c < 16; c++) {
        if (c + 1 < 16) CP_WAIT(1); else CP_WAIT(0);
        __syncthreads();
        const uint32_t sAa = sbase + cbuf * AV_STAGE_BYTES;
        const uint32_t sBa = sAa + 18432u;
#pragma unroll
        for (int ks = 0; ks < 4; ks++) {
            uint32_t z0 = zw[c * 32 + ks * 8 + kq];
            uint32_t z1 = zw[c * 32 + ks * 8 + kq + 4];
            uint32_t bf[4][2];
#pragma unroll
            for (int np = 0; np < 2; np++) {
                uint32_t baddr = sBa + (ks * 16 + tkrow) * 144u
                               + (wn * 32 + np * 16) * 2 + tnoff;
                ldsm_x4t(bf[np*2][0], bf[np*2][1], bf[np*2+1][0], bf[np*2+1][1], baddr);
            }
#pragma unroll
            for (int ni = 0; ni < 4; ni++) {
                bf[ni][0] = bmul2(bf[ni][0], z0);
                bf[ni][1] = bmul2(bf[ni][1], z1);
            }
#pragma unroll
            for (int mi = 0; mi < 2; mi++) {
                uint32_t a0, a1, a2, a3;
                uint32_t aaddr = sAa + (wm * 32 + mi * 16 + lane15) * 144u + ks * 32u + aseg;
                ldsm_x4(a0, a1, a2, a3, aaddr);
#pragma unroll
                for (int ni = 0; ni < 4; ni++)
                    mma_bf16(acc[mi][ni], a0, a1, a2, a3, bf[ni][0], bf[ni][1]);
            }
        }
        if (c + 2 < 16) {
            int nb = cbuf + 2; if (nb >= 3) nb -= 3;
            issue(c + 2, nb); CP_COMMIT();
        }
        cbuf = (cbuf == 2) ? 0 : cbuf + 1;
    }

    __syncthreads();
    uint32_t* pst = smem;
#pragma unroll
    for (int mi = 0; mi < 2; mi++) {
        int rl = wm * 32 + mi * 16 + grp;
#pragma unroll
        for (int ni = 0; ni < 4; ni++) {
            int cl = wn * 32 + ni * 8 + kq * 2;
            pst[rl * 36 + (cl >> 1)]       = pack_bf162(acc[mi][ni][0], acc[mi][ni][1]);
            pst[(rl + 8) * 36 + (cl >> 1)] = pack_bf162(acc[mi][ni][2], acc[mi][ni][3]);
        }
    }
    __syncthreads();
    const int fr = tid >> 3, fc = tid & 7;
#pragma unroll
    for (int p = 0; p < 4; p++) {
        int row = fr + p * 32;
        uint4 v = *(const uint4*)((const char*)smem + row * 144 + fc * 16);
        *(uint4*)(g_parth + (size_t)(b * TT + m0 + row) * DM + h * DKK + fc * 8) = v;
    }
}

// ===== fused producers: x->bf16, Wqkv/Wo transpose-repacks, W1/W2 -> fp16 ========
// blockIdx ranges: [0,8192) round_x; [8192,8448) qkv; [8448,8704) wo; [8704,12800) w12
#define PROD_BLOCKS 12800

__global__ void __launch_bounds__(256) producers(
    const float* __restrict__ x,
    const float* __restrict__ Wq, const float* __restrict__ Wk,
    const float* __restrict__ Wv, const float* __restrict__ Wo,
    const float* __restrict__ W1, const float* __restrict__ W2)
{
    __shared__ float sm[64][65];
    const int bid = blockIdx.x, tid = threadIdx.x;
    if (bid < 8192) {
        int i = bid * 256 + tid;
        float4 v = ((const float4*)x)[i];
        uint32_t* o = (uint32_t*)g_xh;
        o[i * 2]     = pack_bf162(v.x, v.y);
        o[i * 2 + 1] = pack_bf162(v.z, v.w);
    } else if (bid < 8448) {
        const float QSCALE = 0.125f * 1.4426950408889634f;
        int idx = bid - 8192;
        int h = idx >> 4, d0 = (idx & 15) * 64;
        const float* srcs[3] = {Wq, Wk, Wv};
#pragma unroll
        for (int m = 0; m < 3; m++) {
            const float* W = srcs[m];
#pragma unroll
            for (int j = 0; j < 16; j++) {
                int ix = tid + j * 256;
                int dr = ix >> 6, kk = ix & 63;
                sm[dr][kk] = W[(size_t)(h * DM + d0 + dr) * DKK + kk];
            }
            __syncthreads();
            float scale = (m == 0) ? QSCALE : 1.f;
#pragma unroll
            for (int j = 0; j < 16; j++) {
                int ix = tid + j * 256;
                int kk = ix >> 6, dr = ix & 63;
                g_Wqkvh[(size_t)(m * 1024 + h * 64 + kk) * DM + d0 + dr]
                    = __float2bfloat16(sm[dr][kk] * scale);
            }
            __syncthreads();
        }
    } else if (bid < 8704) {
        int idx = bid - 8448;
        int n0 = (idx & 15) * 64, k0 = (idx >> 4) * 64;
#pragma unroll
        for (int j = 0; j < 16; j++) {
            int ix = tid + j * 256;
            int r = ix >> 6, c = ix & 63;
            sm[r][c] = Wo[(size_t)(k0 + r) * DM + n0 + c];
        }
        __syncthreads();
#pragma unroll
        for (int j = 0; j < 16; j++) {
            int ix = tid + j * 256;
            int c = ix >> 6, r = ix & 63;
            g_Worh[(size_t)(n0 + c) * DM + k0 + r] = __float2bfloat16(sm[r][c]);
        }
    } else {
        int i = (bid - 8704) * 256 + tid;
        float4 v1 = ((const float4*)W1)[i];
        float4 v2 = ((const float4*)W2)[i];
        uint32_t* o1 = (uint32_t*)g_W1h;
        uint32_t* o2 = (uint32_t*)g_W2h;
        o1[i * 2]     = pack_f162(v1.x, v1.y);
        o1[i * 2 + 1] = pack_f162(v1.z, v1.w);
        o2[i * 2]     = pack_f162(v2.x, v2.y);
        o2[i * 2 + 1] = pack_f162(v2.z, v2.w);
    }
}

// ---------------- pseudo-norm (float4 vectorized) ---------------------------------
template <int MODE>
__global__ void __launch_bounds__(256) pnorm_kernel(const float* __restrict__ in,
                                                    float* __restrict__ out,
                                                    __half* __restrict__ outh) {
    int row = blockIdx.x;
    const float4* p4 = (const float4*)(in + (size_t)row * DM);
    float4 v = p4[threadIdx.x];
    float s = v.x + v.y + v.z + v.w;
    float s2 = fmaf(v.x, v.x, fmaf(v.y, v.y, fmaf(v.z, v.z, v.w * v.w)));
    __shared__ float sh[2][8];
#pragma unroll
    for (int o = 16; o > 0; o >>= 1) {
        s  += __shfl_down_sync(0xffffffffu, s, o);
        s2 += __shfl_down_sync(0xffffffffu, s2, o);
    }
    int wid = threadIdx.x >> 5, lane = threadIdx.x & 31;
    if (lane == 0) { sh[0][wid] = s; sh[1][wid] = s2; }
    __syncthreads();
    __shared__ float bsub;
    if (threadIdx.x == 0) {
        float ts = 0.f, ts2 = 0.f;
#pragma unroll
        for (int i = 0; i < 8; i++) { ts += sh[0][i]; ts2 += sh[1][i]; }
        float mean = ts * (1.f / 1024.f);
        float var = (ts2 - 1024.f * mean * mean) * (1.f / 1023.f);
        bsub = mean + sqrtf(fmaxf(var, 0.f));
    }
    __syncthreads();
    float sub = bsub;
    float4 o4 = {v.x - sub, v.y - sub, v.z - sub, v.w - sub};
    ((float4*)(out + (size_t)row * DM))[threadIdx.x] = o4;
    if (MODE == 1) {
        uint2 h2;
        h2.x = pack_f162(o4.x, o4.y);
        h2.y = pack_f162(o4.z, o4.w);
        ((uint2*)(outh + (size_t)row * DM))[threadIdx.x] = h2;
    }
}

// ---------------- launch ----------------------------------------------------------
extern "C" void kernel_launch(void* const* d_in, const int* in_sizes, int n_in,
                              void* d_out, int out_size) {
    const float* x  = (const float*)d_in[0];
    const float* Wq = (const float*)d_in[1];
    const float* Wk = (const float*)d_in[2];
    const float* Wv = (const float*)d_in[3];
    const float* Wo = (const float*)d_in[4];
    const float* W1 = (const float*)d_in[5];
    const float* b1 = (const float*)d_in[6];
    const float* W2 = (const float*)d_in[7];
    const float* b2 = (const float*)d_in[8];
    float* out = (float*)d_out;

    __nv_bfloat16 *pXh, *pWqkvh, *pWorh, *pQKVh, *pParth;
    __half *pW1h, *pW2h, *pOut1h, *pFfhh;
    float *pOut1, *pOut2;
    cudaGetSymbolAddress((void**)&pXh,    g_xh);
    cudaGetSymbolAddress((void**)&pWqkvh, g_Wqkvh);
    cudaGetSymbolAddress((void**)&pWorh,  g_Worh);
    cudaGetSymbolAddress((void**)&pQKVh,  g_QKVh);
    cudaGetSymbolAddress((void**)&pParth, g_parth);
    cudaGetSymbolAddress((void**)&pW1h,   g_W1h);
    cudaGetSymbolAddress((void**)&pW2h,   g_W2h);
    cudaGetSymbolAddress((void**)&pOut1h, g_out1h);
    cudaGetSymbolAddress((void**)&pFfhh,  g_ffhh);
    cudaGetSymbolAddress((void**)&pOut1,  g_out1);
    cudaGetSymbolAddress((void**)&pOut2,  g_out2);

    cudaFuncSetAttribute((const void*)gemm_h<4,0>, cudaFuncAttributeMaxDynamicSharedMemorySize, GM_SMEM_BYTES);
    cudaFuncSetAttribute((const void*)gemm_h<1,0>, cudaFuncAttributeMaxDynamicSharedMemorySize, GM_SMEM_BYTES);
    cudaFuncSetAttribute((const void*)gemm_h<2,1>, cudaFuncAttributeMaxDynamicSharedMemorySize, GM_SMEM_BYTES);
    cudaFuncSetAttribute((const void*)gemm_h<3,1>, cudaFuncAttributeMaxDynamicSharedMemorySize, GM_SMEM_BYTES);
    cudaFuncSetAttribute(scores_bf, cudaFuncAttributeMaxDynamicSharedMemorySize, SC_SMEM_BYTES);
    cudaFuncSetAttribute(av_bf,     cudaFuncAttributeMaxDynamicSharedMemorySize, AV_SMEM_BYTES);

    // fused producers (single launch)
    producers<<<PROD_BLOCKS, 256>>>(x, Wq, Wk, Wv, Wo, W1, W2);

    // fused QKV projection (bf16)
    gemm_h<4,0><<<dim3(QKVN / 128, BT / 128), 256, GM_SMEM_BYTES>>>(
        pXh, DM, pWqkvh, DM, pQKVh, QKVN, DM, nullptr, nullptr, 0);

    // attention, batched in 4 groups of 32 bh (P slice L2-resident)
    for (int g = 0; g < 4; g++) {
        scores_bf<<<dim3(8, 8, 32), 256, SC_SMEM_BYTES>>>(g * 32);
        av_bf<<<dim3(8, 32), 256, AV_SMEM_BYTES>>>(g * 32);
    }

    // Wo (bf16) + residual (fp32 x) -> out1 fp32; pnorm emits fp32 + fp16
    gemm_h<1,0><<<dim3(DM / 128, BT / 128), 256, GM_SMEM_BYTES>>>(
        pParth, DM, pWorh, DM, pOut1, DM, DM, nullptr, x, DM);
    pnorm_kernel<1><<<BT, 256>>>(pOut1, pOut1, pOut1h);

    // FF (fp16)
    gemm_h<2,1><<<dim3(FFI / 128, BT / 128), 256, GM_SMEM_BYTES>>>(
        pOut1h, DM, pW1h, DM, pFfhh, FFI, DM, b1, nullptr, 0);
    gemm_h<3,1><<<dim3(DM / 128, BT / 128), 256, GM_SMEM_BYTES>>>(
        pFfhh, FFI, pW2h, FFI, pOut2, DM, FFI, b2, pOut1, DM);

    // final pseudo-norm -> output
    pnorm_kernel<0><<<BT, 256>>>(pOut2, out, nullptr);
}

// round 17
// speedup vs baseline: 1.0260x; 1.0260x over previous
#include <cuda_runtime.h>
#include <cuda_bf16.h>
#include <cuda_fp16.h>
#include <cstdint>
#include <math.h>

#define BQ   8
#define TT   1024
#define DM   1024
#define NH   16
#define DKK  64
#define FFI  4096
#define BT   (BQ*TT)   // 8192 rows
#define BHN  (BQ*NH)   // 128 (b,h) pairs
#define QKVN 3072

// ---------------- scratch (static device globals) --------------------------------
__device__ __nv_bfloat16 g_xh[BT*DM];                 // x in bf16
__device__ __nv_bfloat16 g_Wqkvh[QKVN*DM];            // [n][k] bf16 (Q cols prescaled)
__device__ __nv_bfloat16 g_Worh[DM*DM];               // Wo^T bf16
__device__ __nv_bfloat16 g_QKVh[(size_t)BT*QKVN];     // QKV bf16
__device__ __nv_bfloat16 g_Sh[(size_t)BHN*TT*TT];     // P bf16 (256 MB)
__device__ __nv_bfloat16 g_parth[BT*DM];              // attention out bf16
__device__ __half g_W1h[FFI*DM];                      // W1 fp16 [f][d]
__device__ __half g_W2h[DM*FFI];                      // W2 fp16 [d][f]
__device__ __half g_out1h[BT*DM];                     // out1 fp16 (GEMM A)
__device__ __half g_ffhh[(size_t)BT*FFI];             // FF hidden fp16
__device__ float g_zpart[BHN*8*TT];
__device__ float g_out1[BT*DM];                       // out1 fp32 (residual)
__device__ float g_out2[BT*DM];

// ================= helpers =======================================================
__device__ __forceinline__ uint32_t smem_to_u32(const void* p) {
    uint32_t a;
    asm("{ .reg .u64 t; cvta.to.shared.u64 t, %1; cvt.u32.u64 %0, t; }" : "=r"(a) : "l"(p));
    return a;
}
__device__ __forceinline__ float ex2f(float x) {
    float r;
    asm("ex2.approx.f32 %0, %1;" : "=f"(r) : "f"(x));
    return r;
}
__device__ __forceinline__ uint32_t pack_bf162(float lo, float hi) {
    uint32_t r;
    asm("cvt.rn.bf16x2.f32 %0, %1, %2;" : "=r"(r) : "f"(hi), "f"(lo));
    return r;
}
__device__ __forceinline__ uint32_t pack_f162(float lo, float hi) {
    uint32_t r;
    asm("cvt.rn.f16x2.f32 %0, %1, %2;" : "=r"(r) : "f"(hi), "f"(lo));
    return r;
}
__device__ __forceinline__ uint32_t bmul2(uint32_t a, uint32_t b) {
    uint32_t r;
    asm("mul.rn.bf16x2 %0, %1, %2;" : "=r"(r) : "r"(a), "r"(b));
    return r;
}
__device__ __forceinline__ void cpasync16(uint32_t dst, const void* src) {
    asm volatile("cp.async.cg.shared.global [%0], [%1], 16;" :: "r"(dst), "l"(src));
}
#define CP_COMMIT() asm volatile("cp.async.commit_group;" ::: "memory")
#define CP_WAIT(n)  asm volatile("cp.async.wait_group %0;" :: "n"(n) : "memory")

__device__ __forceinline__ void ldsm_x4(uint32_t& r0, uint32_t& r1, uint32_t& r2,
                                        uint32_t& r3, uint32_t addr) {
    asm volatile("ldmatrix.sync.aligned.m8n8.x4.shared.b16 {%0,%1,%2,%3}, [%4];"
                 : "=r"(r0), "=r"(r1), "=r"(r2), "=r"(r3) : "r"(addr));
}
__device__ __forceinline__ void ldsm_x4t(uint32_t& r0, uint32_t& r1, uint32_t& r2,
                                         uint32_t& r3, uint32_t addr) {
    asm volatile("ldmatrix.sync.aligned.m8n8.x4.trans.shared.b16 {%0,%1,%2,%3}, [%4];"
                 : "=r"(r0), "=r"(r1), "=r"(r2), "=r"(r3) : "r"(addr));
}

__device__ __forceinline__ void mma_bf16(float* c, uint32_t a0, uint32_t a1,
                                         uint32_t a2, uint32_t a3,
                                         uint32_t b0, uint32_t b1) {
    asm volatile(
        "mma.sync.aligned.m16n8k16.row.col.f32.bf16.bf16.f32 "
        "{%0,%1,%2,%3}, {%4,%5,%6,%7}, {%8,%9}, {%0,%1,%2,%3};"
        : "+f"(c[0]), "+f"(c[1]), "+f"(c[2]), "+f"(c[3])
        : "r"(a0), "r"(a1), "r"(a2), "r"(a3), "r"(b0), "r"(b1));
}
__device__ __forceinline__ void mma_fp16(float* c, uint32_t a0, uint32_t a1,
                                         uint32_t a2, uint32_t a3,
                                         uint32_t b0, uint32_t b1) {
    asm volatile(
        "mma.sync.aligned.m16n8k16.row.col.f32.f16.f16.f32 "
        "{%0,%1,%2,%3}, {%4,%5,%6,%7}, {%8,%9}, {%0,%1,%2,%3};"
        : "+f"(c[0]), "+f"(c[1]), "+f"(c[2]), "+f"(c[3])
        : "r"(a0), "r"(a1), "r"(a2), "r"(a3), "r"(b0), "r"(b1));
}

// ================= half-precision dense GEMM (R14) ===============================
#define GM_STAGE_BYTES 36864u
#define GM_SMEM_BYTES  (3*36864)

template <int EPI, int FMT>
__global__ void __launch_bounds__(256, 2) gemm_h(
    const void* __restrict__ Av, int lda,
    const void* __restrict__ Bv, int ldb,
    void* __restrict__ Cv, int ldc,
    int K,
    const float* __restrict__ bias,
    const float* __restrict__ res, int ldres)
{
    extern __shared__ uint32_t smem[];
    const int tid = threadIdx.x;
    const int wid = tid >> 5, lane = tid & 31;
    const int wm = wid >> 2, wn = wid & 3;
    const int grp = lane >> 2, kq = lane & 3;
    const int m0 = blockIdx.y * 128, n0 = blockIdx.x * 128;

    const uint16_t* Ab = (const uint16_t*)Av + (size_t)m0 * lda;
    const uint16_t* Bb = (const uint16_t*)Bv + (size_t)n0 * ldb;
    const uint32_t sbase = smem_to_u32(smem);

    const uint32_t lane15 = lane & 15;
    const uint32_t aseg = (lane >> 4) * 16;
    const uint32_t brow = ((lane >> 4) << 3) + (lane & 7);
    const uint32_t bseg = ((lane >> 3) & 1) * 16;

    float acc[4][4][4] = {};
    const int NC = K / 64;
    const int lr = tid >> 3, lseg = tid & 7;

    auto issue = [&](int c, int buf) {
        const int k0 = c * 64;
        const uint32_t sA = sbase + buf * GM_STAGE_BYTES;
        const uint32_t sB = sA + 18432u;
#pragma unroll
        for (int j = 0; j < 4; j++) {
            int rr = lr + j * 32;
            cpasync16(sA + rr * 144u + lseg * 16u, Ab + (size_t)rr * lda + k0 + lseg * 8);
            cpasync16(sB + rr * 144u + lseg * 16u, Bb + (size_t)rr * ldb + k0 + lseg * 8);
        }
    };

    issue(0, 0); CP_COMMIT();
    issue(1, 1); CP_COMMIT();

    int cbuf = 0;
    for (int c = 0; c < NC; c++) {
        if (c + 1 < NC) CP_WAIT(1); else CP_WAIT(0);
        __syncthreads();
        const uint32_t sAa = sbase + cbuf * GM_STAGE_BYTES;
        const uint32_t sBa = sAa + 18432u;
#pragma unroll
        for (int ks = 0; ks < 4; ks++) {
            uint32_t bf[4][2];
#pragma unroll
            for (int np = 0; np < 2; np++) {
                uint32_t baddr = sBa + (wn * 32 + np * 16 + brow) * 144u + ks * 32u + bseg;
                ldsm_x4(bf[np*2][0], bf[np*2][1], bf[np*2+1][0], bf[np*2+1][1], baddr);
            }
#pragma unroll
            for (int mi = 0; mi < 4; mi++) {
                uint32_t a0, a1, a2, a3;
                uint32_t aaddr = sAa + (wm * 64 + mi * 16 + lane15) * 144u + ks * 32u + aseg;
                ldsm_x4(a0, a1, a2, a3, aaddr);
#pragma unroll
                for (int ni = 0; ni < 4; ni++) {
                    if (FMT == 0) mma_bf16(acc[mi][ni], a0, a1, a2, a3, bf[ni][0], bf[ni][1]);
                    else          mma_fp16(acc[mi][ni], a0, a1, a2, a3, bf[ni][0], bf[ni][1]);
                }
            }
        }
        if (c + 2 < NC) {
            int nb = cbuf + 2; if (nb >= 3) nb -= 3;
            issue(c + 2, nb); CP_COMMIT();
        }
        cbuf = (cbuf == 2) ? 0 : cbuf + 1;
    }

    if (EPI == 4 || EPI == 2) {
        __syncthreads();
        uint32_t* pst = smem;
#pragma unroll
        for (int mi = 0; mi < 4; mi++) {
            int rl = wm * 64 + mi * 16 + grp;
#pragma unroll
            for (int ni = 0; ni < 4; ni++) {
                int cl = wn * 32 + ni * 8 + kq * 2;
                float v00 = acc[mi][ni][0], v01 = acc[mi][ni][1];
                float v10 = acc[mi][ni][2], v11 = acc[mi][ni][3];
                if (EPI == 2) {
                    int colg = n0 + cl;
                    float b0 = bias[colg], b1 = bias[colg + 1];
                    v00 = fmaxf(v00 + b0, 0.f); v01 = fmaxf(v01 + b1, 0.f);
                    v10 = fmaxf(v10 + b0, 0.f); v11 = fmaxf(v11 + b1, 0.f);
                }
                pst[rl * 68 + (cl >> 1)]       = FMT ? pack_f162(v00, v01) : pack_bf162(v00, v01);
                pst[(rl + 8) * 68 + (cl >> 1)] = FMT ? pack_f162(v10, v11) : pack_bf162(v10, v11);
            }
        }
        __syncthreads();
        uint16_t* C = (uint16_t*)Cv;
        const int fr = tid >> 4, fc = tid & 15;
#pragma unroll
        for (int p = 0; p < 8; p++) {
            int row = fr + p * 16;
            uint4 v = *(const uint4*)((const char*)smem + row * 272 + fc * 16);
            *(uint4*)(C + (size_t)(m0 + row) * ldc + n0 + fc * 8) = v;
        }
    } else {
#pragma unroll
        for (int mi = 0; mi < 4; mi++) {
            int row = m0 + wm * 64 + mi * 16 + grp;
#pragma unroll
            for (int ni = 0; ni < 4; ni++) {
                int col = n0 + wn * 32 + ni * 8 + kq * 2;
                float v00 = acc[mi][ni][0], v01 = acc[mi][ni][1];
                float v10 = acc[mi][ni][2], v11 = acc[mi][ni][3];
                float* C = (float*)Cv;
                float2 r0 = *(const float2*)(res + (size_t)row * ldres + col);
                float2 r1 = *(const float2*)(res + (size_t)(row + 8) * ldres + col);
                if (EPI == 3) {
                    float b0 = bias[col], b1 = bias[col + 1];
                    v00 += b0; v01 += b1; v10 += b0; v11 += b1;
                }
                float2 o0 = {v00 + r0.x, v01 + r0.y};
                float2 o1 = {v10 + r1.x, v11 + r1.y};
                *(float2*)(C + (size_t)row * ldc + col) = o0;
                *(float2*)(C + (size_t)(row + 8) * ldc + col) = o1;
            }
        }
    }
}

// ===== scores: P = bf16(exp2(Q'·K^T)), SMEM-staged coalesced store ===============
#define SC_SMEM_BYTES 36864

__global__ void __launch_bounds__(256, 2) scores_bf() {
    extern __shared__ uint32_t smem[];
    const int tid = threadIdx.x;
    const int wid = tid >> 5, lane = tid & 31;
    const int wm = wid >> 2, wn = wid & 3;
    const int grp = lane >> 2, kq = lane & 3;
    const int bh = blockIdx.z, b = bh >> 4, h = bh & 15;
    const int q0 = blockIdx.y * 128, s0 = blockIdx.x * 128;

    const __nv_bfloat16* Ab = g_QKVh + (size_t)(b * TT + q0) * QKVN + h * DKK;
    const __nv_bfloat16* Bb = g_QKVh + (size_t)(b * TT + s0) * QKVN + 1024 + h * DKK;
    const uint32_t sbase = smem_to_u32(smem);
    const uint32_t sB0 = sbase + 18432u;

    const uint32_t lane15 = lane & 15;
    const uint32_t aseg = (lane >> 4) * 16;
    const uint32_t brow = ((lane >> 4) << 3) + (lane & 7);
    const uint32_t bseg = ((lane >> 3) & 1) * 16;

#pragma unroll
    for (int j = 0; j < 4; j++) {
        int idx = tid + j * 256;
        int rr = idx >> 3, seg = idx & 7;
        cpasync16(sbase + rr * 144u + seg * 16u, Ab + (size_t)rr * QKVN + seg * 8);
        cpasync16(sB0 + rr * 144u + seg * 16u, Bb + (size_t)rr * QKVN + seg * 8);
    }
    CP_COMMIT(); CP_WAIT(0);
    __syncthreads();

    float acc[4][4][4] = {};
#pragma unroll
    for (int ks = 0; ks < 4; ks++) {
        uint32_t bf[4][2];
#pragma unroll
        for (int np = 0; np < 2; np++) {
            uint32_t baddr = sB0 + (wn * 32 + np * 16 + brow) * 144u + ks * 32u + bseg;
            ldsm_x4(bf[np*2][0], bf[np*2][1], bf[np*2+1][0], bf[np*2+1][1], baddr);
        }
#pragma unroll
        for (int mi = 0; mi < 4; mi++) {
            uint32_t a0, a1, a2, a3;
            uint32_t aaddr = sbase + (wm * 64 + mi * 16 + lane15) * 144u + ks * 32u + aseg;
            ldsm_x4(a0, a1, a2, a3, aaddr);
#pragma unroll
            for (int ni = 0; ni < 4; ni++)
                mma_bf16(acc[mi][ni], a0, a1, a2, a3, bf[ni][0], bf[ni][1]);
        }
    }
    __syncthreads();   // A/B tiles dead past here; smem reused for P staging

    uint32_t* pst = smem;
    float* zsm = (float*)(smem + 8704);
    float cs0[4] = {}, cs1[4] = {};
#pragma unroll
    for (int mi = 0; mi < 4; mi++) {
        int rl = wm * 64 + mi * 16 + grp;
#pragma unroll
        for (int ni = 0; ni < 4; ni++) {
            int cl = wn * 32 + ni * 8 + kq * 2;
            float p00 = ex2f(acc[mi][ni][0]);
            float p01 = ex2f(acc[mi][ni][1]);
            float p10 = ex2f(acc[mi][ni][2]);
            float p11 = ex2f(acc[mi][ni][3]);
            cs0[ni] += p00 + p10;
            cs1[ni] += p01 + p11;
            pst[rl * 68 + (cl >> 1)]       = pack_bf162(p00, p01);
            pst[(rl + 8) * 68 + (cl >> 1)] = pack_bf162(p10, p11);
        }
    }
#pragma unroll
    for (int ni = 0; ni < 4; ni++) {
#pragma unroll
        for (int o = 16; o >= 4; o >>= 1) {
            cs0[ni] += __shfl_down_sync(0xffffffffu, cs0[ni], o);
            cs1[ni] += __shfl_down_sync(0xffffffffu, cs1[ni], o);
        }
        if (grp == 0) {
            int c = wn * 32 + ni * 8 + kq * 2;
            zsm[wm * 128 + c] = cs0[ni];
            zsm[wm * 128 + c + 1] = cs1[ni];
        }
    }
    __syncthreads();

    __nv_bfloat16* Sb = g_Sh + (size_t)bh * TT * TT;
    const int fr = tid >> 4, fc = tid & 15;
#pragma unroll
    for (int p = 0; p < 8; p++) {
        int row = fr + p * 16;
        uint4 v = *(const uint4*)((const char*)smem + row * 272 + fc * 16);
        *(uint4*)(Sb + (size_t)(q0 + row) * TT + s0 + fc * 8) = v;
    }
    if (tid < 128)
        g_zpart[(bh * 8 + blockIdx.y) * TT + s0 + tid] = zsm[tid] + zsm[128 + tid];
}

// ===== AV GEMM (bf16): part = P x (V*zinv), V direct via ldmatrix.trans (R15) ====
#define AV_STAGE_BYTES 27648u
#define AV_SMEM_BYTES (3*27648 + 2048)

__global__ void __launch_bounds__(256, 2) av_bf() {
    extern __shared__ uint32_t smem[];
    const int tid = threadIdx.x;
    const int wid = tid >> 5, lane = tid & 31;
    const int wm = wid >> 1, wn = wid & 1;
    const int grp = lane >> 2, kq = lane & 3;
    const int bh = blockIdx.y, b = bh >> 4, h = bh & 15;
    const int m0 = blockIdx.x * 128;

    const __nv_bfloat16* Ab = g_Sh + (size_t)bh * TT * TT + (size_t)m0 * TT;
    const __nv_bfloat16* Vb = g_QKVh + (size_t)(b * TT) * QKVN + 2048 + h * DKK;
    const uint32_t sbase = smem_to_u32(smem);

    const uint32_t lane15 = lane & 15;
    const uint32_t aseg = (lane >> 4) * 16;
    const uint32_t tkrow = (lane & 7) + ((lane >> 3) & 1) * 8;
    const uint32_t tnoff = (lane >> 4) * 16;

    uint32_t* zw = smem + 20736;
    for (int t = tid; t < 512; t += 256) {
        float z0 = 0.f, z1 = 0.f;
#pragma unroll
        for (int q = 0; q < 8; q++) {
            z0 += g_zpart[(bh * 8 + q) * TT + 2 * t];
            z1 += g_zpart[(bh * 8 + q) * TT + 2 * t + 1];
        }
        zw[t] = pack_bf162(1.f / z0, 1.f / z1);
    }

    float acc[2][4][4] = {};
    const int lr = tid >> 3, lseg = tid & 7;

    auto issue = [&](int c, int buf) {
        const int k0 = c * 64;
        const uint32_t sA = sbase + buf * AV_STAGE_BYTES;
        const uint32_t sB = sA + 18432u;
#pragma unroll
        for (int j = 0; j < 4; j++) {
            int rr = lr + j * 32;
            cpasync16(sA + rr * 144u + lseg * 16u, Ab + (size_t)rr * TT + k0 + lseg * 8);
        }
#pragma unroll
        for (int j = 0; j < 2; j++) {
            int rr = lr + j * 32;
            cpasync16(sB + rr * 144u + lseg * 16u, Vb + (size_t)(k0 + rr) * QKVN + lseg * 8);
        }
    };

    issue(0, 0); CP_COMMIT();
    issue(1, 1); CP_COMMIT();

    int cbuf = 0;
    for (int c = 0; c < 16; c++) {
        if (c + 1 < 16) CP_WAIT(1); else CP_WAIT(0);
        __syncthreads();
        const uint32_t sAa = sbase + cbuf * AV_STAGE_BYTES;
        const uint32_t sBa = sAa + 18432u;
#pragma unroll
        for (int ks = 0; ks < 4; ks++) {
            uint32_t z0 = zw[c * 32 + ks * 8 + kq];
            uint32_t z1 = zw[c * 32 + ks * 8 + kq + 4];
            uint32_t bf[4][2];
#pragma unroll
            for (int np = 0; np < 2; np++) {
                uint32_t baddr = sBa + (ks * 16 + tkrow) * 144u
                               + (wn * 32 + np * 16) * 2 + tnoff;
                ldsm_x4t(bf[np*2][0], bf[np*2][1], bf[np*2+1][0], bf[np*2+1][1], baddr);
            }
#pragma unroll
            for (int ni = 0; ni < 4; ni++) {
                bf[ni][0] = bmul2(bf[ni][0], z0);
                bf[ni][1] = bmul2(bf[ni][1], z1);
            }
#pragma unroll
            for (int mi = 0; mi < 2; mi++) {
                uint32_t a0, a1, a2, a3;
                uint32_t aaddr = sAa + (wm * 32 + mi * 16 + lane15) * 144u + ks * 32u + aseg;
                ldsm_x4(a0, a1, a2, a3, aaddr);
#pragma unroll
                for (int ni = 0; ni < 4; ni++)
                    mma_bf16(acc[mi][ni], a0, a1, a2, a3, bf[ni][0], bf[ni][1]);
            }
        }
        if (c + 2 < 16) {
            int nb = cbuf + 2; if (nb >= 3) nb -= 3;
            issue(c + 2, nb); CP_COMMIT();
        }
        cbuf = (cbuf == 2) ? 0 : cbuf + 1;
    }

    __syncthreads();
    uint32_t* pst = smem;
#pragma unroll
    for (int mi = 0; mi < 2; mi++) {
        int rl = wm * 32 + mi * 16 + grp;
#pragma unroll
        for (int ni = 0; ni < 4; ni++) {
            int cl = wn * 32 + ni * 8 + kq * 2;
            pst[rl * 36 + (cl >> 1)]       = pack_bf162(acc[mi][ni][0], acc[mi][ni][1]);
            pst[(rl + 8) * 36 + (cl >> 1)] = pack_bf162(acc[mi][ni][2], acc[mi][ni][3]);
        }
    }
    __syncthreads();
    const int fr = tid >> 3, fc = tid & 7;
#pragma unroll
    for (int p = 0; p < 4; p++) {
        int row = fr + p * 32;
        uint4 v = *(const uint4*)((const char*)smem + row * 144 + fc * 16);
        *(uint4*)(g_parth + (size_t)(b * TT + m0 + row) * DM + h * DKK + fc * 8) = v;
    }
}

// ===== fused producers (R16) ======================================================
#define PROD_BLOCKS 12800

__global__ void __launch_bounds__(256) producers(
    const float* __restrict__ x,
    const float* __restrict__ Wq, const float* __restrict__ Wk,
    const float* __restrict__ Wv, const float* __restrict__ Wo,
    const float* __restrict__ W1, const float* __restrict__ W2)
{
    __shared__ float sm[64][65];
    const int bid = blockIdx.x, tid = threadIdx.x;
    if (bid < 8192) {
        int i = bid * 256 + tid;
        float4 v = ((const float4*)x)[i];
        uint32_t* o = (uint32_t*)g_xh;
        o[i * 2]     = pack_bf162(v.x, v.y);
        o[i * 2 + 1] = pack_bf162(v.z, v.w);
    } else if (bid < 8448) {
        const float QSCALE = 0.125f * 1.4426950408889634f;
        int idx = bid - 8192;
        int h = idx >> 4, d0 = (idx & 15) * 64;
        const float* srcs[3] = {Wq, Wk, Wv};
#pragma unroll
        for (int m = 0; m < 3; m++) {
            const float* W = srcs[m];
#pragma unroll
            for (int j = 0; j < 16; j++) {
                int ix = tid + j * 256;
                int dr = ix >> 6, kk = ix & 63;
                sm[dr][kk] = W[(size_t)(h * DM + d0 + dr) * DKK + kk];
            }
            __syncthreads();
            float scale = (m == 0) ? QSCALE : 1.f;
#pragma unroll
            for (int j = 0; j < 16; j++) {
                int ix = tid + j * 256;
                int kk = ix >> 6, dr = ix & 63;
                g_Wqkvh[(size_t)(m * 1024 + h * 64 + kk) * DM + d0 + dr]
                    = __float2bfloat16(sm[dr][kk] * scale);
            }
            __syncthreads();
        }
    } else if (bid < 8704) {
        int idx = bid - 8448;
        int n0 = (idx & 15) * 64, k0 = (idx >> 4) * 64;
#pragma unroll
        for (int j = 0; j < 16; j++) {
            int ix = tid + j * 256;
            int r = ix >> 6, c = ix & 63;
            sm[r][c] = Wo[(size_t)(k0 + r) * DM + n0 + c];
        }
        __syncthreads();
#pragma unroll
        for (int j = 0; j < 16; j++) {
            int ix = tid + j * 256;
            int c = ix >> 6, r = ix & 63;
            g_Worh[(size_t)(n0 + c) * DM + k0 + r] = __float2bfloat16(sm[r][c]);
        }
    } else {
        int i = (bid - 8704) * 256 + tid;
        float4 v1 = ((const float4*)W1)[i];
        float4 v2 = ((const float4*)W2)[i];
        uint32_t* o1 = (uint32_t*)g_W1h;
        uint32_t* o2 = (uint32_t*)g_W2h;
        o1[i * 2]     = pack_f162(v1.x, v1.y);
        o1[i * 2 + 1] = pack_f162(v1.z, v1.w);
        o2[i * 2]     = pack_f162(v2.x, v2.y);
        o2[i * 2 + 1] = pack_f162(v2.z, v2.w);
    }
}

// ---------------- pseudo-norm (float4 vectorized, R16) -----------------------------
template <int MODE>
__global__ void __launch_bounds__(256) pnorm_kernel(const float* __restrict__ in,
                                                    float* __restrict__ out,
                                                    __half* __restrict__ outh) {
    int row = blockIdx.x;
    const float4* p4 = (const float4*)(in + (size_t)row * DM);
    float4 v = p4[threadIdx.x];
    float s = v.x + v.y + v.z + v.w;
    float s2 = fmaf(v.x, v.x, fmaf(v.y, v.y, fmaf(v.z, v.z, v.w * v.w)));
    __shared__ float sh[2][8];
#pragma unroll
    for (int o = 16; o > 0; o >>= 1) {
        s  += __shfl_down_sync(0xffffffffu, s, o);
        s2 += __shfl_down_sync(0xffffffffu, s2, o);
    }
    int wid = threadIdx.x >> 5, lane = threadIdx.x & 31;
    if (lane == 0) { sh[0][wid] = s; sh[1][wid] = s2; }
    __syncthreads();
    __shared__ float bsub;
    if (threadIdx.x == 0) {
        float ts = 0.f, ts2 = 0.f;
#pragma unroll
        for (int i = 0; i < 8; i++) { ts += sh[0][i]; ts2 += sh[1][i]; }
        float mean = ts * (1.f / 1024.f);
        float var = (ts2 - 1024.f * mean * mean) * (1.f / 1023.f);
        bsub = mean + sqrtf(fmaxf(var, 0.f));
    }
    __syncthreads();
    float sub = bsub;
    float4 o4 = {v.x - sub, v.y - sub, v.z - sub, v.w - sub};
    ((float4*)(out + (size_t)row * DM))[threadIdx.x] = o4;
    if (MODE == 1) {
        uint2 h2;
        h2.x = pack_f162(o4.x, o4.y);
        h2.y = pack_f162(o4.z, o4.w);
        ((uint2*)(outh + (size_t)row * DM))[threadIdx.x] = h2;
    }
}

// ---------------- launch ----------------------------------------------------------
extern "C" void kernel_launch(void* const* d_in, const int* in_sizes, int n_in,
                              void* d_out, int out_size) {
    const float* x  = (const float*)d_in[0];
    const float* Wq = (const float*)d_in[1];
    const float* Wk = (const float*)d_in[2];
    const float* Wv = (const float*)d_in[3];
    const float* Wo = (const float*)d_in[4];
    const float* W1 = (const float*)d_in[5];
    const float* b1 = (const float*)d_in[6];
    const float* W2 = (const float*)d_in[7];
    const float* b2 = (const float*)d_in[8];
    float* out = (float*)d_out;

    __nv_bfloat16 *pXh, *pWqkvh, *pWorh, *pQKVh, *pParth;
    __half *pW1h, *pW2h, *pOut1h, *pFfhh;
    float *pOut1, *pOut2;
    cudaGetSymbolAddress((void**)&pXh,    g_xh);
    cudaGetSymbolAddress((void**)&pWqkvh, g_Wqkvh);
    cudaGetSymbolAddress((void**)&pWorh,  g_Worh);
    cudaGetSymbolAddress((void**)&pQKVh,  g_QKVh);
    cudaGetSymbolAddress((void**)&pParth, g_parth);
    cudaGetSymbolAddress((void**)&pW1h,   g_W1h);
    cudaGetSymbolAddress((void**)&pW2h,   g_W2h);
    cudaGetSymbolAddress((void**)&pOut1h, g_out1h);
    cudaGetSymbolAddress((void**)&pFfhh,  g_ffhh);
    cudaGetSymbolAddress((void**)&pOut1,  g_out1);
    cudaGetSymbolAddress((void**)&pOut2,  g_out2);

    cudaFuncSetAttribute((const void*)gemm_h<4,0>, cudaFuncAttributeMaxDynamicSharedMemorySize, GM_SMEM_BYTES);
    cudaFuncSetAttribute((const void*)gemm_h<1,0>, cudaFuncAttributeMaxDynamicSharedMemorySize, GM_SMEM_BYTES);
    cudaFuncSetAttribute((const void*)gemm_h<2,1>, cudaFuncAttributeMaxDynamicSharedMemorySize, GM_SMEM_BYTES);
    cudaFuncSetAttribute((const void*)gemm_h<3,1>, cudaFuncAttributeMaxDynamicSharedMemorySize, GM_SMEM_BYTES);
    cudaFuncSetAttribute(scores_bf, cudaFuncAttributeMaxDynamicSharedMemorySize, SC_SMEM_BYTES);
    cudaFuncSetAttribute(av_bf,     cudaFuncAttributeMaxDynamicSharedMemorySize, AV_SMEM_BYTES);

    // fused producers (single launch)
    producers<<<PROD_BLOCKS, 256>>>(x, Wq, Wk, Wv, Wo, W1, W2);

    // fused QKV projection (bf16)
    gemm_h<4,0><<<dim3(QKVN / 128, BT / 128), 256, GM_SMEM_BYTES>>>(
        pXh, DM, pWqkvh, DM, pQKVh, QKVN, DM, nullptr, nullptr, 0);

    // attention: single full-grid launches (L2 batching measured ineffective)
    scores_bf<<<dim3(8, 8, BHN), 256, SC_SMEM_BYTES>>>();
    av_bf<<<dim3(8, BHN), 256, AV_SMEM_BYTES>>>();

    // Wo (bf16) + residual (fp32 x) -> out1 fp32; pnorm emits fp32 + fp16
    gemm_h<1,0><<<dim3(DM / 128, BT / 128), 256, GM_SMEM_BYTES>>>(
        pParth, DM, pWorh, DM, pOut1, DM, DM, nullptr, x, DM);
    pnorm_kernel<1><<<BT, 256>>>(pOut1, pOut1, pOut1h);

    // FF (fp16)
    gemm_h<2,1><<<dim3(FFI / 128, BT / 128), 256, GM_SMEM_BYTES>>>(
        pOut1h, DM, pW1h, DM, pFfhh, FFI, DM, b1, nullptr, 0);
    gemm_h<3,1><<<dim3(DM / 128, BT / 128), 256, GM_SMEM_BYTES>>>(
        pFfhh, FFI, pW2h, FFI, pOut2, DM, FFI, b2, pOut1, DM);

    // final pseudo-norm -> output
    pnorm_kernel<0><<<BT, 256>>>(pOut2, out, nullptr);
}